// round 7
// baseline (speedup 1.0000x reference)
#include <cuda_runtime.h>
#include <cuda_bf16.h>

#define NUM_CLASSES 16384
#define FEAT_DIM    1024
#define ALPHA       0.5f
#define NSLOT       64
#define SLOT_STRIDE 16      // 16 doubles = 128 B -> distinct LTS partitions
#define NCOMB       64      // combine blocks
#define GRID_K1     (148 * 16)   // persistent: one wave of 128-thread blocks

// Scratch (zero at process start; combine_kernel re-zeroes everything each
// run, so every graph replay starts from a clean state).
__device__ int          g_counts[NUM_CLASSES];
__device__ float2       g_vw[NUM_CLASSES];            // per-class (Sum uv, Sum v^2)
__device__ double       g_uslot[NSLOT * SLOT_STRIDE]; // strided slots for Sum u^2
__device__ double       g_bslot[NCOMB * SLOT_STRIDE]; // combine per-block partials
__device__ unsigned int g_ticket;

// ---------------------------------------------------------------------------
// K1: persistent heavy kernel. 2368 blocks x 128 threads, grid-stride over
// rows (~7 rows/block). Per row:
//   u = y_pred[i] - centers[j],  v = centers[jj] - y_pred[j]
//   U = sum u^2, V = sum u*v, W = sum v^2  (scale deferred to K2)
// NO smem, NO __syncthreads: each warp shfl-reduces its own partial and its
// lane 0 fires atomics, so warps pipeline independently across rows.
// ---------------------------------------------------------------------------
__global__ __launch_bounds__(128)
void centerloss_kernel(const int*   __restrict__ y_true,
                       const float* __restrict__ y_pred,
                       const float* __restrict__ centers) {
    const int tid = threadIdx.x;
    const int lid = tid & 31;
    const bool warp0 = (tid < 32);

    for (int row = blockIdx.x; row < NUM_CLASSES; row += GRID_K1) {
        const int j  = y_true[row];
        const int jj = y_true[j];

        const float4* A = (const float4*)(y_pred  + (size_t)row * FEAT_DIM);
        const float4* B = (const float4*)(centers + (size_t)j   * FEAT_DIM);
        const float4* C = (const float4*)(centers + (size_t)jj  * FEAT_DIM);
        const float4* D = (const float4*)(y_pred  + (size_t)j   * FEAT_DIM);

        const int t0 = tid;
        const int t1 = tid + 128;

        // 8 independent 16B loads, front-batched
        float4 a0 = A[t0], a1 = A[t1];
        float4 b0 = B[t0], b1 = B[t1];
        float4 c0 = C[t0], c1 = C[t1];
        float4 d0 = D[t0], d1 = D[t1];

        float su = 0.0f, suv = 0.0f, sv = 0.0f;
        {
            float ux = a0.x - b0.x, vx = c0.x - d0.x;
            float uy = a0.y - b0.y, vy = c0.y - d0.y;
            float uz = a0.z - b0.z, vz = c0.z - d0.z;
            float uw = a0.w - b0.w, vw = c0.w - d0.w;
            su  += ux*ux + uy*uy + uz*uz + uw*uw;
            suv += ux*vx + uy*vy + uz*vz + uw*vw;
            sv  += vx*vx + vy*vy + vz*vz + vw*vw;
        }
        {
            float ux = a1.x - b1.x, vx = c1.x - d1.x;
            float uy = a1.y - b1.y, vy = c1.y - d1.y;
            float uz = a1.z - b1.z, vz = c1.z - d1.z;
            float uw = a1.w - b1.w, vw = c1.w - d1.w;
            su  += ux*ux + uy*uy + uz*uz + uw*uw;
            suv += ux*vx + uy*vy + uz*vz + uw*vw;
            sv  += vx*vx + vy*vy + vz*vz + vw*vw;
        }

        // warp-local reduce (no cross-warp combine -> no barrier)
        #pragma unroll
        for (int off = 16; off > 0; off >>= 1) {
            su  += __shfl_xor_sync(0xFFFFFFFFu, su,  off);
            suv += __shfl_xor_sync(0xFFFFFFFFu, suv, off);
            sv  += __shfl_xor_sync(0xFFFFFFFFu, sv,  off);
        }

        if (lid == 0) {
            atomicAdd(&g_vw[jj].x, suv);
            atomicAdd(&g_vw[jj].y, sv);
            atomicAdd(&g_uslot[(row & (NSLOT - 1)) * SLOT_STRIDE], (double)su);
            if (warp0) atomicAdd(&g_counts[j], 1);   // one count per row
        }
    }
}

// ---------------------------------------------------------------------------
// K2: parallel combine + reset. 64 blocks x 256 threads, one class/thread
// per coalesced chunk:
//   term_c = 2*s_c*V_c + s_c^2*W_c,   s_c = ALPHA/(counts[c]+1)
// Block partial -> distinct strided slot (plain store), chunk reset, then
// ticket via atom.add.acq_rel (release for this block's writes; the acquire
// on the LAST increment synchronizes-with all earlier releases, so no
// L1-flushing fence is needed).
// ---------------------------------------------------------------------------
__global__ __launch_bounds__(256)
void combine_kernel(float* __restrict__ out) {
    const int tid = threadIdx.x;
    const int b   = blockIdx.x;
    const int c   = b * 256 + tid;

    const float  cnt = (float)g_counts[c];
    const float2 vw  = g_vw[c];
    const float  s   = ALPHA / (cnt + 1.0f);
    double acc = (double)(2.0f * s * vw.x + s * s * vw.y);

    #pragma unroll
    for (int off = 16; off > 0; off >>= 1)
        acc += __shfl_xor_sync(0xFFFFFFFFu, acc, off);

    __shared__ double dsum[8];
    __shared__ bool   s_last;
    const int wid = tid >> 5;
    const int lid = tid & 31;
    if (lid == 0) dsum[wid] = acc;
    __syncthreads();

    // reset this block's chunk
    g_counts[c] = 0;
    g_vw[c] = make_float2(0.0f, 0.0f);

    if (tid == 0) {
        double v = 0.0;
        #pragma unroll
        for (int w = 0; w < 8; w++) v += dsum[w];
        g_bslot[b * SLOT_STRIDE] = v;          // distinct slot, no atomic
        unsigned int old;
        asm volatile("atom.acq_rel.gpu.global.add.u32 %0, [%1], 1;"
                     : "=r"(old) : "l"(&g_ticket) : "memory");
        s_last = (old == NCOMB - 1);
    }
    __syncthreads();

    if (s_last) {
        // 128 slots: tid<64 -> bslot, 64<=tid<128 -> uslot
        double v = 0.0;
        if (tid < NCOMB)              v = g_bslot[tid * SLOT_STRIDE];
        else if (tid < NCOMB + NSLOT) v = g_uslot[(tid - NCOMB) * SLOT_STRIDE];
        #pragma unroll
        for (int off = 16; off > 0; off >>= 1)
            v += __shfl_xor_sync(0xFFFFFFFFu, v, off);
        if (lid == 0) dsum[wid] = v;
        __syncthreads();
        if (tid == 0) {
            double tot = dsum[0] + dsum[1] + dsum[2] + dsum[3];
            out[0] = (float)(tot / ((double)NUM_CLASSES * (double)FEAT_DIM));
            g_ticket = 0u;
        }
        if (tid < NCOMB)              g_bslot[tid * SLOT_STRIDE] = 0.0;
        else if (tid < NCOMB + NSLOT) g_uslot[(tid - NCOMB) * SLOT_STRIDE] = 0.0;
    }
}

extern "C" void kernel_launch(void* const* d_in, const int* in_sizes, int n_in,
                              void* d_out, int out_size) {
    const int*   y_true  = (const int*)  d_in[0];
    const float* y_pred  = (const float*)d_in[1];
    const float* centers = (const float*)d_in[2];
    float* out = (float*)d_out;

    centerloss_kernel<<<GRID_K1, 128>>>(y_true, y_pred, centers);
    combine_kernel<<<NCOMB, 256>>>(out);
}

// round 8
// speedup vs baseline: 1.0754x; 1.0754x over previous
#include <cuda_runtime.h>
#include <cuda_bf16.h>

#define NUM_CLASSES 16384
#define FEAT_DIM    1024
#define ALPHA       0.5f
#define NSLOT       64
#define SLOT_STRIDE 16   // 16 doubles = 128 B -> distinct LTS partitions
#define NCOMB       64   // combine blocks (== NSLOT, one uslot per block)

// Scratch (zero at process start; combine_kernel re-zeroes everything each
// run, so every graph replay starts from a clean state).
__device__ int          g_counts[NUM_CLASSES];
__device__ float2       g_vw[NUM_CLASSES];            // per-class (Sum uv, Sum v^2)
__device__ double       g_uslot[NSLOT * SLOT_STRIDE]; // strided slots for Sum u^2
__device__ double       g_acc;
__device__ unsigned int g_ticket;

// ---------------------------------------------------------------------------
// K1 (identical to the R6 best): one block (128 thr) per row, 8 independent
// LDG.128 per thread.
//   u = y_pred[i] - centers[j],  v = centers[jj] - y_pred[j]
//   U = sum u^2, V = sum u*v, W = sum v^2   (scale s deferred to K2)
// Fused bincount via RED counts[j]; no counts dependency, low regs.
// ---------------------------------------------------------------------------
__global__ __launch_bounds__(128)
void centerloss_kernel(const int*   __restrict__ y_true,
                       const float* __restrict__ y_pred,
                       const float* __restrict__ centers) {
    const int row = blockIdx.x;
    const int tid = threadIdx.x;

    const int j  = y_true[row];
    const int jj = y_true[j];

    const float4* A = (const float4*)(y_pred  + (size_t)row * FEAT_DIM);
    const float4* B = (const float4*)(centers + (size_t)j   * FEAT_DIM);
    const float4* C = (const float4*)(centers + (size_t)jj  * FEAT_DIM);
    const float4* D = (const float4*)(y_pred  + (size_t)j   * FEAT_DIM);

    const int t0 = tid;
    const int t1 = tid + 128;

    // front-batched: 8 independent 16B loads
    float4 a0 = A[t0], a1 = A[t1];
    float4 b0 = B[t0], b1 = B[t1];
    float4 c0 = C[t0], c1 = C[t1];
    float4 d0 = D[t0], d1 = D[t1];

    float su = 0.0f, suv = 0.0f, sv = 0.0f;
    {
        float ux = a0.x - b0.x, vx = c0.x - d0.x;
        float uy = a0.y - b0.y, vy = c0.y - d0.y;
        float uz = a0.z - b0.z, vz = c0.z - d0.z;
        float uw = a0.w - b0.w, vw = c0.w - d0.w;
        su  += ux*ux + uy*uy + uz*uz + uw*uw;
        suv += ux*vx + uy*vy + uz*vz + uw*vw;
        sv  += vx*vx + vy*vy + vz*vz + vw*vw;
    }
    {
        float ux = a1.x - b1.x, vx = c1.x - d1.x;
        float uy = a1.y - b1.y, vy = c1.y - d1.y;
        float uz = a1.z - b1.z, vz = c1.z - d1.z;
        float uw = a1.w - b1.w, vw = c1.w - d1.w;
        su  += ux*ux + uy*uy + uz*uz + uw*uw;
        suv += ux*vx + uy*vy + uz*vz + uw*vw;
        sv  += vx*vx + vy*vy + vz*vz + vw*vw;
    }

    #pragma unroll
    for (int off = 16; off > 0; off >>= 1) {
        su  += __shfl_xor_sync(0xFFFFFFFFu, su,  off);
        suv += __shfl_xor_sync(0xFFFFFFFFu, suv, off);
        sv  += __shfl_xor_sync(0xFFFFFFFFu, sv,  off);
    }

    __shared__ float3 warp_sums[4];
    const int wid = tid >> 5;
    const int lid = tid & 31;
    if (lid == 0) warp_sums[wid] = make_float3(su, suv, sv);
    __syncthreads();

    if (tid == 0) {
        float U = warp_sums[0].x + warp_sums[1].x + warp_sums[2].x + warp_sums[3].x;
        float V = warp_sums[0].y + warp_sums[1].y + warp_sums[2].y + warp_sums[3].y;
        float W = warp_sums[0].z + warp_sums[1].z + warp_sums[2].z + warp_sums[3].z;
        atomicAdd(&g_counts[j], 1);                  // fused bincount
        atomicAdd(&g_vw[jj].x, V);
        atomicAdd(&g_vw[jj].y, W);
        atomicAdd(&g_uslot[(row & (NSLOT - 1)) * SLOT_STRIDE], (double)U);
    }
}

// ---------------------------------------------------------------------------
// K2: parallel combine + reset, single-phase tail.
// 64 blocks x 256 threads, one class per thread (coalesced chunk):
//   term_c = 2*s_c*V_c + s_c^2*W_c,   s_c = ALPHA/(counts[c]+1)
// Block b folds g_uslot[b] into its partial, one relaxed double atomic into
// g_acc, then an acq_rel ticket. Last block reads g_acc once -> out, and
// resets g_acc/ticket. Each block resets its own class chunk + uslot.
// ---------------------------------------------------------------------------
__global__ __launch_bounds__(256)
void combine_kernel(float* __restrict__ out) {
    const int tid = threadIdx.x;
    const int b   = blockIdx.x;
    const int c   = b * 256 + tid;

    const float  cnt = (float)g_counts[c];
    const float2 vw  = g_vw[c];
    const float  s   = ALPHA / (cnt + 1.0f);
    double acc = (double)(2.0f * s * vw.x + s * s * vw.y);

    // block-reduce 256 doubles
    #pragma unroll
    for (int off = 16; off > 0; off >>= 1)
        acc += __shfl_xor_sync(0xFFFFFFFFu, acc, off);

    __shared__ double dsum[8];
    __shared__ bool   s_last;
    const int wid = tid >> 5;
    const int lid = tid & 31;
    if (lid == 0) dsum[wid] = acc;
    __syncthreads();

    // reset this block's chunk (values already consumed above)
    g_counts[c] = 0;
    g_vw[c] = make_float2(0.0f, 0.0f);

    if (tid == 0) {
        double v = 0.0;
        #pragma unroll
        for (int w = 0; w < 8; w++) v += dsum[w];
        v += g_uslot[b * SLOT_STRIDE];       // fold this block's U slot
        g_uslot[b * SLOT_STRIDE] = 0.0;      // and reset it
        atomicAdd(&g_acc, v);                // relaxed; ordered by ticket release
        unsigned int old;
        asm volatile("atom.acq_rel.gpu.global.add.u32 %0, [%1], 1;"
                     : "=r"(old) : "l"(&g_ticket) : "memory");
        s_last = (old == NCOMB - 1);
    }
    __syncthreads();

    if (s_last && tid == 0) {
        double tot = g_acc;                  // visible via ticket acquire
        out[0] = (float)(tot / ((double)NUM_CLASSES * (double)FEAT_DIM));
        g_acc    = 0.0;
        g_ticket = 0u;
    }
}

extern "C" void kernel_launch(void* const* d_in, const int* in_sizes, int n_in,
                              void* d_out, int out_size) {
    const int*   y_true  = (const int*)  d_in[0];
    const float* y_pred  = (const float*)d_in[1];
    const float* centers = (const float*)d_in[2];
    float* out = (float*)d_out;

    centerloss_kernel<<<NUM_CLASSES, 128>>>(y_true, y_pred, centers);
    combine_kernel<<<NCOMB, 256>>>(out);
}